// round 3
// baseline (speedup 1.0000x reference)
#include <cuda_runtime.h>

#define NUM_BINS 15
#define NTHREADS 256
#define TILE     512
#define MAXQB    64

// ---------------- device scratch (no allocations allowed) ----------------
__device__ float g_tr_rate[NUM_BINS];
__device__ float g_te_rate[NUM_BINS];
__device__ float g_cnt;
__device__ float g_part[NUM_BINS * MAXQB];

// constants
#define C2   (1.4426950408889634f / 0.18f)   /* log2e / (2*BW*BW), BW=0.3 */
#define KN   (0.5654866776461628f)           /* 2*pi*BW*BW */
#define STEP (1.0f / 15.0f)

__device__ __forceinline__ float ex2_approx(float x) {
    float r;
    asm("ex2.approx.ftz.f32 %0, %1;" : "=f"(r) : "f"(x));
    return r;
}

// ---------------- kernel A: bin rates + correct count ----------------
__global__ void __launch_bounds__(NTHREADS) stats_kernel(
    const int* __restrict__ y, const int* __restrict__ pred,
    const float* __restrict__ trp, const float* __restrict__ tep,
    int B, int NTR, int NTE)
{
    __shared__ float red[NTHREADS];
    int bin = blockIdx.x;
    int tid = threadIdx.x;

    if (bin < NUM_BINS) {
        float lo = bin * STEP;
        float hi = (bin + 1) * STEP;
        float c1 = 0.f;
        for (int i = tid; i < NTR; i += NTHREADS) {
            float p = trp[i];
            c1 += (p > lo && p <= hi) ? 1.f : 0.f;
        }
        red[tid] = c1; __syncthreads();
        for (int s = NTHREADS / 2; s > 0; s >>= 1) {
            if (tid < s) red[tid] += red[tid + s];
            __syncthreads();
        }
        if (tid == 0) g_tr_rate[bin] = red[0] / (float)NTR;
        __syncthreads();

        float c2 = 0.f;
        for (int i = tid; i < NTE; i += NTHREADS) {
            float p = tep[i];
            c2 += (p > lo && p <= hi) ? 1.f : 0.f;
        }
        red[tid] = c2; __syncthreads();
        for (int s = NTHREADS / 2; s > 0; s >>= 1) {
            if (tid < s) red[tid] += red[tid + s];
            __syncthreads();
        }
        if (tid == 0) g_te_rate[bin] = red[0] / (float)NTE;
    } else {
        float c = 0.f;
        for (int i = tid; i < B; i += NTHREADS)
            c += (y[i] == pred[i]) ? 1.f : 0.f;
        red[tid] = c; __syncthreads();
        for (int s = NTHREADS / 2; s > 0; s >>= 1) {
            if (tid < s) red[tid] += red[tid + s];
            __syncthreads();
        }
        if (tid == 0) g_cnt = red[0];
    }
}

// ---------------- kernel B: fused KDE main ----------------
__global__ void __launch_bounds__(NTHREADS) main_kernel(
    const float* __restrict__ mc,   // (15, NMC, 2)
    const float* __restrict__ trx,  // (NTRX, 2)
    const float* __restrict__ tex,  // (NTEX, 2)
    const float* __restrict__ bx,   // (B, 2)
    const int*   __restrict__ y,
    const int*   __restrict__ pred,
    const float* __restrict__ W,    // (2, 10)
    const float* __restrict__ bvec, // (10,)
    int NMC, int NTRX, int NTEX, int B)
{
    __shared__ float4 sd[TILE];
    __shared__ float red[NTHREADS];

    const int bin = blockIdx.y;
    const int qi  = blockIdx.x * NTHREADS + threadIdx.x;
    const bool active = qi < NMC;

    float qx = 0.f, qy = 0.f;
    if (active) {
        qx = mc[(size_t)(bin * NMC + qi) * 2 + 0];
        qy = mc[(size_t)(bin * NMC + qi) * 2 + 1];
    }
    const float Cm = 2.f * C2;
    const float A  = -C2 * (qx * qx + qy * qy);

    float s_sum[3];

    #pragma unroll 1
    for (int ph = 0; ph < 3; ph++) {
        const float* src = (ph == 0) ? trx : (ph == 1) ? tex : bx;
        const int    n   = (ph == 0) ? NTRX : (ph == 1) ? NTEX : B;
        float a0 = 0.f, a1 = 0.f;

        for (int base = 0; base < n; base += TILE) {
            int m = min(TILE, n - base);
            for (int j = threadIdx.x; j < m; j += NTHREADS) {
                float dx = src[(size_t)(base + j) * 2 + 0];
                float dy = src[(size_t)(base + j) * 2 + 1];
                float wt = 1.f;
                if (ph == 2) wt = (y[base + j] == pred[base + j]) ? 1.f : 0.f;
                sd[j] = make_float4(Cm * dx, Cm * dy,
                                    -C2 * (dx * dx + dy * dy), wt);
            }
            __syncthreads();

            if (ph < 2) {
                #pragma unroll 8
                for (int j = 0; j < m; j++) {
                    float4 p = sd[j];
                    float arg = fmaf(p.x, qx, fmaf(p.y, qy, p.z + A));
                    float e = ex2_approx(arg);
                    if (j & 1) a1 += e; else a0 += e;
                }
            } else {
                #pragma unroll 8
                for (int j = 0; j < m; j++) {
                    float4 p = sd[j];
                    float arg = fmaf(p.x, qx, fmaf(p.y, qy, p.z + A));
                    float e = ex2_approx(arg);
                    if (j & 1) a1 = fmaf(e, p.w, a1);
                    else       a0 = fmaf(e, p.w, a0);
                }
            }
            __syncthreads();
        }
        s_sum[ph] = a0 + a1;
    }

    float v = 0.f;
    if (active) {
        // hat_s = max softmax of (x @ W + b)
        float lmax = -1e30f;
        float l[10];
        #pragma unroll
        for (int c = 0; c < 10; c++) {
            l[c] = fmaf(qx, W[c], fmaf(qy, W[10 + c], bvec[c]));
            lmax = fmaxf(lmax, l[c]);
        }
        float ssum = 0.f;
        #pragma unroll
        for (int c = 0; c < 10; c++) ssum += __expf(l[c] - lmax);
        float hat_s = 1.f / ssum;

        float lo = bin * STEP;
        float hi = (bin + 1) * STEP;
        float idx = (hat_s >= lo && hat_s <= hi) ? 1.f : 0.f;

        float cnt    = g_cnt;
        float kde_tr = s_sum[0] / ((float)NTRX * KN);
        float kde_te = s_sum[1] / ((float)NTEX * KN);
        float kde_w  = s_sum[2] / (fmaxf(cnt, 1.f) * KN);
        float p_y    = cnt / (float)B;

        float ter = g_te_rate[bin];
        float trr = g_tr_rate[bin];
        float d_t = (ter > 0.f) ? (kde_te / ter) : 0.f;
        float d_s = (trr > 0.f) ? (kde_tr / trr) : 0.f;
        d_t *= idx;
        d_s *= idx;

        float p_hs = kde_w * p_y / (kde_tr + 1e-8f);
        p_hs = fminf(fmaxf(p_hs, 0.f), 1.f);
        v = p_hs * (d_t - d_s);
    }

    red[threadIdx.x] = v;
    __syncthreads();
    for (int s = NTHREADS / 2; s > 0; s >>= 1) {
        if (threadIdx.x < s) red[threadIdx.x] += red[threadIdx.x + s];
        __syncthreads();
    }
    if (threadIdx.x == 0)
        g_part[bin * MAXQB + blockIdx.x] = red[0];
}

// ---------------- kernel C: final combine ----------------
__global__ void final_kernel(float* __restrict__ out, int nqb, int NMC)
{
    int lane = threadIdx.x;  // 32 threads
    float ec = 0.f;
    for (int bin = 0; bin < NUM_BINS; bin++) {
        float s = 0.f;
        for (int j = lane; j < nqb; j += 32) s += g_part[bin * MAXQB + j];
        #pragma unroll
        for (int o = 16; o > 0; o >>= 1) s += __shfl_xor_sync(0xffffffff, s, o);
        float integral = (s / (float)NMC) * 100.0f;  // VOLUME = 100
        float ter = g_te_rate[bin];
        if (ter > 0.f) ec += ter * fabsf(integral);
    }
    if (lane == 0) out[0] = ec;
}

// ---------------- launch ----------------
extern "C" void kernel_launch(void* const* d_in, const int* in_sizes, int n_in,
                              void* d_out, int out_size)
{
    const float* bx   = (const float*)d_in[0];  // batch_train_x (B,2)
    const int*   y    = (const int*)  d_in[1];  // batch_train_y
    const int*   pred = (const int*)  d_in[2];  // train_pred
    const float* trp  = (const float*)d_in[3];  // train_probs
    const float* tep  = (const float*)d_in[4];  // test_probs
    const float* trx  = (const float*)d_in[5];  // train_x (NTR,2)
    const float* tex  = (const float*)d_in[6];  // test_x (NTE,2)
    const float* W    = (const float*)d_in[7];  // (2,10)
    const float* bv   = (const float*)d_in[8];  // (10,)
    const float* mc   = (const float*)d_in[9];  // (15,NMC,2)

    int B    = in_sizes[1];
    int NTR  = in_sizes[3];
    int NTE  = in_sizes[4];
    int NTRX = in_sizes[5] / 2;
    int NTEX = in_sizes[6] / 2;
    int NMC  = in_sizes[9] / (2 * NUM_BINS);
    int nqb  = (NMC + NTHREADS - 1) / NTHREADS;

    stats_kernel<<<NUM_BINS + 1, NTHREADS>>>(y, pred, trp, tep, B, NTR, NTE);

    dim3 grid(nqb, NUM_BINS);
    main_kernel<<<grid, NTHREADS>>>(mc, trx, tex, bx, y, pred, W, bv,
                                    NMC, NTRX, NTEX, B);

    final_kernel<<<1, 32>>>((float*)d_out, nqb, NMC);
}

// round 5
// speedup vs baseline: 4.6814x; 4.6814x over previous
#include <cuda_runtime.h>

#define NUM_BINS 15
#define NMC_CAP  10240
#define NFB_CAP  48      // filter blocks per bin (ceil(NMC/256))
#define QB_CAP   192     // main blocks per bin (ceil(NMC/64))
#define DSPLIT   4
#define TILE     512

#define STEP (1.0f / 15.0f)
#define C2   (1.4426950408889634f / 0.18f)   /* log2e / (2*BW*BW) */
#define KN   (0.5654866776461628f)           /* 2*pi*BW*BW */

// ---------------- device scratch ----------------
__device__ int    g_hist_tr[NUM_BINS];
__device__ int    g_hist_te[NUM_BINS];
__device__ int    g_correct;
__device__ float  g_tr_rate[NUM_BINS];
__device__ float  g_te_rate[NUM_BINS];
__device__ float  g_cntf;
__device__ int    g_fcnt[NUM_BINS * NFB_CAP];
__device__ int    g_foff[NUM_BINS * NFB_CAP];
__device__ int    g_qcnt[NUM_BINS];
__device__ float2 g_q[NUM_BINS * NMC_CAP];
__device__ float  g_ssum[DSPLIT * 3 * NUM_BINS * NMC_CAP];
__device__ float  g_part[NUM_BINS * QB_CAP];

__device__ __forceinline__ float ex2_approx(float x) {
    float r;
    asm("ex2.approx.ftz.f32 %0, %1;" : "=f"(r) : "f"(x));
    return r;
}

// hat_s = max softmax(x@W + b); test membership in bin's [lo,hi] (inclusive)
__device__ __forceinline__ bool pass_bin(float qx, float qy,
                                         const float* __restrict__ W,
                                         const float* __restrict__ bv,
                                         int bin) {
    float l[10];
    float lmax = -1e30f;
    #pragma unroll
    for (int c = 0; c < 10; c++) {
        l[c] = fmaf(qx, W[c], fmaf(qy, W[10 + c], bv[c]));
        lmax = fmaxf(lmax, l[c]);
    }
    float s = 0.f;
    #pragma unroll
    for (int c = 0; c < 10; c++) s += expf(l[c] - lmax);
    float hs = 1.f / s;
    float lo = bin * STEP;
    float hi = (bin + 1) * STEP;
    return (hs >= lo) && (hs <= hi);
}

// ---------------- K0: zero accumulators ----------------
__global__ void init_kernel() {
    int t = threadIdx.x;
    if (t < NUM_BINS) { g_hist_tr[t] = 0; g_hist_te[t] = 0; }
    if (t == 31) g_correct = 0;
}

// ---------------- K1: histograms + correct count (int atomics: deterministic)
__global__ void __launch_bounds__(256) hist_kernel(
    const float* __restrict__ trp, const float* __restrict__ tep,
    const int* __restrict__ y, const int* __restrict__ pred,
    int NTR, int NTE, int B)
{
    __shared__ int sh[NUM_BINS];
    int tid = threadIdx.x;
    int part = blockIdx.x;   // 0..15 train, 16..23 test, 24 correct

    if (part < 24) {
        if (tid < NUM_BINS) sh[tid] = 0;
        __syncthreads();
        const float* src = (part < 16) ? trp : tep;
        int n = (part < 16) ? NTR : NTE;
        int nb = (part < 16) ? 16 : 8;
        int pb = (part < 16) ? part : part - 16;
        for (int i = pb * 256 + tid; i < n; i += nb * 256) {
            float p = src[i];
            int bx = (int)ceilf(p * 15.f) - 1;
            bx = min(14, max(0, bx));
            // exact-predicate fixup
            if (!(p > bx * STEP && p <= (bx + 1) * STEP)) {
                if (p <= bx * STEP) bx--; else bx++;
            }
            if (bx >= 0 && bx < NUM_BINS && p > bx * STEP && p <= (bx + 1) * STEP)
                atomicAdd(&sh[bx], 1);
        }
        __syncthreads();
        if (tid < NUM_BINS && sh[tid]) {
            if (part < 16) atomicAdd(&g_hist_tr[tid], sh[tid]);
            else           atomicAdd(&g_hist_te[tid], sh[tid]);
        }
    } else {
        __shared__ int red[256];
        int c = 0;
        for (int i = tid; i < B; i += 256)
            c += (y[i] == pred[i]) ? 1 : 0;
        red[tid] = c; __syncthreads();
        for (int s = 128; s > 0; s >>= 1) {
            if (tid < s) red[tid] += red[tid + s];
            __syncthreads();
        }
        if (tid == 0) atomicAdd(&g_correct, red[0]);
    }
}

// ---------------- K2: per-block pass counts ----------------
__global__ void __launch_bounds__(256) fcount_kernel(
    const float* __restrict__ mc, const float* __restrict__ W,
    const float* __restrict__ bv, int NMC)
{
    int bin = blockIdx.y;
    int qi  = blockIdx.x * 256 + threadIdx.x;
    bool p = false;
    if (qi < NMC) {
        float qx = mc[(size_t)(bin * NMC + qi) * 2 + 0];
        float qy = mc[(size_t)(bin * NMC + qi) * 2 + 1];
        p = pass_bin(qx, qy, W, bv, bin);
    }
    __shared__ int wsum[8];
    int lane = threadIdx.x & 31, wid = threadIdx.x >> 5;
    int c = __popc(__ballot_sync(0xffffffff, p));
    if (lane == 0) wsum[wid] = c;
    __syncthreads();
    if (threadIdx.x == 0) {
        int t = 0;
        #pragma unroll
        for (int w = 0; w < 8; w++) t += wsum[w];
        g_fcnt[bin * NFB_CAP + blockIdx.x] = t;
    }
}

// ---------------- K3: prefix scan + rates ----------------
__global__ void scan_kernel(int nfb, int NTR, int NTE) {
    int t = threadIdx.x;
    if (t < NUM_BINS) {
        int run = 0;
        for (int f = 0; f < nfb; f++) {
            g_foff[t * NFB_CAP + f] = run;
            run += g_fcnt[t * NFB_CAP + f];
        }
        g_qcnt[t] = run;
        g_tr_rate[t] = (float)g_hist_tr[t] / (float)NTR;
        g_te_rate[t] = (float)g_hist_te[t] / (float)NTE;
    }
    if (t == 31) g_cntf = (float)g_correct;
}

// ---------------- K4: deterministic scatter compaction ----------------
__global__ void __launch_bounds__(256) scatter_kernel(
    const float* __restrict__ mc, const float* __restrict__ W,
    const float* __restrict__ bv, int NMC)
{
    __shared__ int sc[256];
    int bin = blockIdx.y;
    int tid = threadIdx.x;
    int qi  = blockIdx.x * 256 + tid;
    bool p = false;
    float qx = 0.f, qy = 0.f;
    if (qi < NMC) {
        qx = mc[(size_t)(bin * NMC + qi) * 2 + 0];
        qy = mc[(size_t)(bin * NMC + qi) * 2 + 1];
        p = pass_bin(qx, qy, W, bv, bin);
    }
    int f = p ? 1 : 0;
    sc[tid] = f; __syncthreads();
    for (int off = 1; off < 256; off <<= 1) {
        int v = (tid >= off) ? sc[tid - off] : 0;
        __syncthreads();
        sc[tid] += v;
        __syncthreads();
    }
    if (p) {
        int pos = g_foff[bin * NFB_CAP + blockIdx.x] + sc[tid] - 1;
        g_q[bin * NMC_CAP + pos] = make_float2(qx, qy);
    }
}

// ---------------- K5: KDE main over compacted queries ----------------
__global__ void __launch_bounds__(64) main_kernel(
    const float* __restrict__ trx, const float* __restrict__ tex,
    const float* __restrict__ bx,
    const int* __restrict__ y, const int* __restrict__ pred,
    int NTRX, int NTEX, int B)
{
    __shared__ float4 sd[TILE];

    const int bin = blockIdx.y;
    const int z   = blockIdx.z;
    const int cnt = g_qcnt[bin];
    if ((int)(blockIdx.x * 64) >= cnt) return;

    const int  qi  = blockIdx.x * 64 + threadIdx.x;
    const bool act = qi < cnt;
    float2 q = act ? g_q[bin * NMC_CAP + qi] : make_float2(0.f, 0.f);

    const float Cm = 2.f * C2;
    const float A  = -C2 * (q.x * q.x + q.y * q.y);

    #pragma unroll 1
    for (int ph = 0; ph < 3; ph++) {
        const float* src = (ph == 0) ? trx : (ph == 1) ? tex : bx;
        const int    n   = (ph == 0) ? NTRX : (ph == 1) ? NTEX : B;
        const int i0 = (z * n) / DSPLIT;
        const int i1 = ((z + 1) * n) / DSPLIT;
        float a0 = 0.f, a1 = 0.f;

        for (int base = i0; base < i1; base += TILE) {
            int m = min(TILE, i1 - base);
            for (int j = threadIdx.x; j < m; j += 64) {
                float dx = src[(size_t)(base + j) * 2 + 0];
                float dy = src[(size_t)(base + j) * 2 + 1];
                float wt = 1.f;
                if (ph == 2) wt = (y[base + j] == pred[base + j]) ? 1.f : 0.f;
                sd[j] = make_float4(Cm * dx, Cm * dy,
                                    -C2 * (dx * dx + dy * dy), wt);
            }
            __syncthreads();

            if (ph < 2) {
                #pragma unroll 8
                for (int j = 0; j < m; j++) {
                    float4 p = sd[j];
                    float arg = fmaf(p.x, q.x, fmaf(p.y, q.y, p.z + A));
                    float e = ex2_approx(arg);
                    if (j & 1) a1 += e; else a0 += e;
                }
            } else {
                #pragma unroll 8
                for (int j = 0; j < m; j++) {
                    float4 p = sd[j];
                    float arg = fmaf(p.x, q.x, fmaf(p.y, q.y, p.z + A));
                    float e = ex2_approx(arg);
                    if (j & 1) a1 = fmaf(e, p.w, a1);
                    else       a0 = fmaf(e, p.w, a0);
                }
            }
            __syncthreads();
        }
        if (act)
            g_ssum[((size_t)(z * 3 + ph) * NUM_BINS + bin) * NMC_CAP + qi] = a0 + a1;
    }
}

// ---------------- K6: combine partials -> per-block v sums ----------------
__global__ void __launch_bounds__(64) combine_kernel(int NTRX, int NTEX, int B)
{
    __shared__ float red[64];
    const int bin = blockIdx.y;
    const int cnt = g_qcnt[bin];
    const int qi  = blockIdx.x * 64 + threadIdx.x;

    float v = 0.f;
    if (qi < cnt) {
        float s0 = 0.f, s1 = 0.f, s2 = 0.f;
        #pragma unroll
        for (int z = 0; z < DSPLIT; z++) {
            s0 += g_ssum[((size_t)(z * 3 + 0) * NUM_BINS + bin) * NMC_CAP + qi];
            s1 += g_ssum[((size_t)(z * 3 + 1) * NUM_BINS + bin) * NMC_CAP + qi];
            s2 += g_ssum[((size_t)(z * 3 + 2) * NUM_BINS + bin) * NMC_CAP + qi];
        }
        float cntf   = g_cntf;
        float kde_tr = s0 / ((float)NTRX * KN);
        float kde_te = s1 / ((float)NTEX * KN);
        float kde_w  = s2 / (fmaxf(cntf, 1.f) * KN);
        float p_y    = cntf / (float)B;

        float ter = g_te_rate[bin];
        float trr = g_tr_rate[bin];
        float d_t = (ter > 0.f) ? (kde_te / ter) : 0.f;  // idx == 1 by construction
        float d_s = (trr > 0.f) ? (kde_tr / trr) : 0.f;

        float p_hs = kde_w * p_y / (kde_tr + 1e-8f);
        p_hs = fminf(fmaxf(p_hs, 0.f), 1.f);
        v = p_hs * (d_t - d_s);
    }

    red[threadIdx.x] = v; __syncthreads();
    for (int s = 32; s > 0; s >>= 1) {
        if (threadIdx.x < s) red[threadIdx.x] += red[threadIdx.x + s];
        __syncthreads();
    }
    if (threadIdx.x == 0)
        g_part[bin * QB_CAP + blockIdx.x] = red[0];
}

// ---------------- K7: final ----------------
__global__ void final_kernel(float* __restrict__ out, int nqb, int NMC)
{
    int lane = threadIdx.x;  // 32 threads
    float ec = 0.f;
    for (int bin = 0; bin < NUM_BINS; bin++) {
        float s = 0.f;
        for (int j = lane; j < nqb; j += 32) s += g_part[bin * QB_CAP + j];
        #pragma unroll
        for (int o = 16; o > 0; o >>= 1) s += __shfl_xor_sync(0xffffffff, s, o);
        float integral = (s / (float)NMC) * 100.0f;   // VOLUME
        float ter = g_te_rate[bin];
        if (ter > 0.f) ec += ter * fabsf(integral);
    }
    if (lane == 0) out[0] = ec;
}

// ---------------- launch ----------------
extern "C" void kernel_launch(void* const* d_in, const int* in_sizes, int n_in,
                              void* d_out, int out_size)
{
    const float* bx   = (const float*)d_in[0];
    const int*   y    = (const int*)  d_in[1];
    const int*   pred = (const int*)  d_in[2];
    const float* trp  = (const float*)d_in[3];
    const float* tep  = (const float*)d_in[4];
    const float* trx  = (const float*)d_in[5];
    const float* tex  = (const float*)d_in[6];
    const float* W    = (const float*)d_in[7];
    const float* bv   = (const float*)d_in[8];
    const float* mc   = (const float*)d_in[9];

    int B    = in_sizes[1];
    int NTR  = in_sizes[3];
    int NTE  = in_sizes[4];
    int NTRX = in_sizes[5] / 2;
    int NTEX = in_sizes[6] / 2;
    int NMC  = in_sizes[9] / (2 * NUM_BINS);
    int nfb  = (NMC + 255) / 256;
    int nqb  = (NMC + 63) / 64;

    init_kernel<<<1, 32>>>();
    hist_kernel<<<25, 256>>>(trp, tep, y, pred, NTR, NTE, B);

    dim3 fg(nfb, NUM_BINS);
    fcount_kernel<<<fg, 256>>>(mc, W, bv, NMC);
    scan_kernel<<<1, 32>>>(nfb, NTR, NTE);
    scatter_kernel<<<fg, 256>>>(mc, W, bv, NMC);

    dim3 mg(nqb, NUM_BINS, DSPLIT);
    main_kernel<<<mg, 64>>>(trx, tex, bx, y, pred, NTRX, NTEX, B);

    dim3 cg(nqb, NUM_BINS);
    combine_kernel<<<cg, 64>>>(NTRX, NTEX, B);

    final_kernel<<<1, 32>>>((float*)d_out, nqb, NMC);
}

// round 6
// speedup vs baseline: 7.0075x; 1.4969x over previous
#include <cuda_runtime.h>

#define NUM_BINS 15
#define NMC_CAP  10240
#define QB_CAP   80      // ceil(NMC_CAP/128)
#define DSPLIT   12
#define TILE     512

#define STEP (1.0f / 15.0f)
#define C2   (1.4426950408889634f / 0.18f)   /* log2e / (2*BW*BW) */
#define KN   (0.5654866776461628f)           /* 2*pi*BW*BW */

// ---------------- device scratch ----------------
__device__ int    g_hist_tr[NUM_BINS];
__device__ int    g_hist_te[NUM_BINS];
__device__ int    g_correct;
__device__ float  g_tr_rate[NUM_BINS];
__device__ float  g_te_rate[NUM_BINS];
__device__ float  g_cntf;
__device__ int    g_qcnt[NUM_BINS];
__device__ float2 g_q[NUM_BINS * NMC_CAP];
__device__ float  g_ssum[DSPLIT * 3 * NUM_BINS * NMC_CAP];  // ~22 MB
__device__ float  g_part[NUM_BINS * QB_CAP];

__device__ __forceinline__ float ex2_approx(float x) {
    float r;
    asm("ex2.approx.ftz.f32 %0, %1;" : "=f"(r) : "f"(x));
    return r;
}

// hat_s = max softmax(x@W + b); membership in bin's [lo,hi] (inclusive)
__device__ __forceinline__ bool pass_bin(float qx, float qy,
                                         const float* __restrict__ W,
                                         const float* __restrict__ bv,
                                         int bin) {
    float l[10];
    float lmax = -1e30f;
    #pragma unroll
    for (int c = 0; c < 10; c++) {
        l[c] = fmaf(qx, W[c], fmaf(qy, W[10 + c], bv[c]));
        lmax = fmaxf(lmax, l[c]);
    }
    float s = 0.f;
    #pragma unroll
    for (int c = 0; c < 10; c++) s += expf(l[c] - lmax);
    float hs = 1.f / s;
    float lo = bin * STEP;
    float hi = (bin + 1) * STEP;
    return (hs >= lo) && (hs <= hi);
}

// ---------------- K0: zero accumulators ----------------
__global__ void init_kernel() {
    int t = threadIdx.x;
    if (t < NUM_BINS) { g_hist_tr[t] = 0; g_hist_te[t] = 0; }
    if (t == 31) g_correct = 0;
}

// ---------------- K1: histograms + correct count (int atomics) ----------------
__global__ void __launch_bounds__(256) hist_kernel(
    const float* __restrict__ trp, const float* __restrict__ tep,
    const int* __restrict__ y, const int* __restrict__ pred,
    int NTR, int NTE, int B)
{
    __shared__ int sh[NUM_BINS];
    int tid = threadIdx.x;
    int part = blockIdx.x;   // 0..15 train, 16..23 test, 24 correct

    if (part < 24) {
        if (tid < NUM_BINS) sh[tid] = 0;
        __syncthreads();
        const float* src = (part < 16) ? trp : tep;
        int n  = (part < 16) ? NTR : NTE;
        int nb = (part < 16) ? 16 : 8;
        int pb = (part < 16) ? part : part - 16;
        for (int i = pb * 256 + tid; i < n; i += nb * 256) {
            float p = src[i];
            int bx = (int)ceilf(p * 15.f) - 1;
            bx = min(14, max(0, bx));
            if (!(p > bx * STEP && p <= (bx + 1) * STEP)) {
                if (p <= bx * STEP) bx--; else bx++;
            }
            if (bx >= 0 && bx < NUM_BINS && p > bx * STEP && p <= (bx + 1) * STEP)
                atomicAdd(&sh[bx], 1);
        }
        __syncthreads();
        if (tid < NUM_BINS && sh[tid]) {
            if (part < 16) atomicAdd(&g_hist_tr[tid], sh[tid]);
            else           atomicAdd(&g_hist_te[tid], sh[tid]);
        }
    } else {
        __shared__ int red[256];
        int c = 0;
        for (int i = tid; i < B; i += 256)
            c += (y[i] == pred[i]) ? 1 : 0;
        red[tid] = c; __syncthreads();
        for (int s = 128; s > 0; s >>= 1) {
            if (tid < s) red[tid] += red[tid + s];
            __syncthreads();
        }
        if (tid == 0) atomicAdd(&g_correct, red[0]);
    }
}

// ---------------- K2: fused filter + deterministic compaction + rates --------
// One block per bin (1024 threads). Warp-ballot compaction; serial 32-entry
// warp-base scan on thread 0 keeps ordering fully deterministic.
__global__ void __launch_bounds__(1024) filter_kernel(
    const float* __restrict__ mc, const float* __restrict__ W,
    const float* __restrict__ bv, int NMC, int NTR, int NTE)
{
    __shared__ int wtot[32];
    __shared__ int wbase[32];
    __shared__ int runbase;

    const int bin  = blockIdx.x;
    const int tid  = threadIdx.x;
    const int lane = tid & 31;
    const int wid  = tid >> 5;

    if (tid == 0) runbase = 0;
    __syncthreads();

    for (int base = 0; base < NMC; base += 1024) {
        int qi = base + tid;
        bool p = false;
        float qx = 0.f, qy = 0.f;
        if (qi < NMC) {
            qx = mc[(size_t)(bin * NMC + qi) * 2 + 0];
            qy = mc[(size_t)(bin * NMC + qi) * 2 + 1];
            p = pass_bin(qx, qy, W, bv, bin);
        }
        unsigned mask = __ballot_sync(0xffffffffu, p);
        int off = __popc(mask & ((1u << lane) - 1u));
        if (lane == 0) wtot[wid] = __popc(mask);
        __syncthreads();
        if (tid == 0) {
            int r = runbase;
            #pragma unroll
            for (int w = 0; w < 32; w++) { wbase[w] = r; r += wtot[w]; }
            runbase = r;
        }
        __syncthreads();
        if (p)
            g_q[bin * NMC_CAP + wbase[wid] + off] = make_float2(qx, qy);
        __syncthreads();
    }

    if (tid == 0) {
        g_qcnt[bin] = runbase;
        g_tr_rate[bin] = (float)g_hist_tr[bin] / (float)NTR;
        g_te_rate[bin] = (float)g_hist_te[bin] / (float)NTE;
        if (bin == 0) g_cntf = (float)g_correct;
    }
}

// ---------------- K3: KDE main over compacted queries ----------------
__global__ void __launch_bounds__(128) main_kernel(
    const float* __restrict__ trx, const float* __restrict__ tex,
    const float* __restrict__ bx,
    const int* __restrict__ y, const int* __restrict__ pred,
    int NTRX, int NTEX, int B)
{
    __shared__ float4 sd[TILE];

    const int bin = blockIdx.y;
    const int z   = blockIdx.z;
    const int cnt = g_qcnt[bin];
    if ((int)(blockIdx.x * 128) >= cnt) return;

    const int  qi  = blockIdx.x * 128 + threadIdx.x;
    const bool act = qi < cnt;
    float2 q = act ? g_q[bin * NMC_CAP + qi] : make_float2(0.f, 0.f);

    const float Cm = 2.f * C2;
    const float A  = -C2 * (q.x * q.x + q.y * q.y);

    #pragma unroll 1
    for (int ph = 0; ph < 3; ph++) {
        const float* src = (ph == 0) ? trx : (ph == 1) ? tex : bx;
        const int    n   = (ph == 0) ? NTRX : (ph == 1) ? NTEX : B;
        const int i0 = (z * n) / DSPLIT;
        const int i1 = ((z + 1) * n) / DSPLIT;
        float a0 = 0.f, a1 = 0.f;

        for (int base = i0; base < i1; base += TILE) {
            int m = min(TILE, i1 - base);
            for (int j = threadIdx.x; j < m; j += 128) {
                float dx = src[(size_t)(base + j) * 2 + 0];
                float dy = src[(size_t)(base + j) * 2 + 1];
                float wt = 1.f;
                if (ph == 2) wt = (y[base + j] == pred[base + j]) ? 1.f : 0.f;
                sd[j] = make_float4(Cm * dx, Cm * dy,
                                    -C2 * (dx * dx + dy * dy), wt);
            }
            __syncthreads();

            if (ph < 2) {
                #pragma unroll 8
                for (int j = 0; j < m; j++) {
                    float4 p = sd[j];
                    float arg = fmaf(p.x, q.x, fmaf(p.y, q.y, p.z + A));
                    float e = ex2_approx(arg);
                    if (j & 1) a1 += e; else a0 += e;
                }
            } else {
                #pragma unroll 8
                for (int j = 0; j < m; j++) {
                    float4 p = sd[j];
                    float arg = fmaf(p.x, q.x, fmaf(p.y, q.y, p.z + A));
                    float e = ex2_approx(arg);
                    if (j & 1) a1 = fmaf(e, p.w, a1);
                    else       a0 = fmaf(e, p.w, a0);
                }
            }
            __syncthreads();
        }
        if (act)
            g_ssum[((size_t)(z * 3 + ph) * NUM_BINS + bin) * NMC_CAP + qi] = a0 + a1;
    }
}

// ---------------- K4: combine partials -> per-block v sums ----------------
__global__ void __launch_bounds__(128) combine_kernel(int NTRX, int NTEX, int B)
{
    __shared__ float red[128];
    const int bin = blockIdx.y;
    const int cnt = g_qcnt[bin];
    const int qi  = blockIdx.x * 128 + threadIdx.x;

    float v = 0.f;
    if (qi < cnt) {
        float s0 = 0.f, s1 = 0.f, s2 = 0.f;
        #pragma unroll
        for (int z = 0; z < DSPLIT; z++) {
            s0 += g_ssum[((size_t)(z * 3 + 0) * NUM_BINS + bin) * NMC_CAP + qi];
            s1 += g_ssum[((size_t)(z * 3 + 1) * NUM_BINS + bin) * NMC_CAP + qi];
            s2 += g_ssum[((size_t)(z * 3 + 2) * NUM_BINS + bin) * NMC_CAP + qi];
        }
        float cntf   = g_cntf;
        float kde_tr = s0 / ((float)NTRX * KN);
        float kde_te = s1 / ((float)NTEX * KN);
        float kde_w  = s2 / (fmaxf(cntf, 1.f) * KN);
        float p_y    = cntf / (float)B;

        float ter = g_te_rate[bin];
        float trr = g_tr_rate[bin];
        float d_t = (ter > 0.f) ? (kde_te / ter) : 0.f;  // idx == 1 by construction
        float d_s = (trr > 0.f) ? (kde_tr / trr) : 0.f;

        float p_hs = kde_w * p_y / (kde_tr + 1e-8f);
        p_hs = fminf(fmaxf(p_hs, 0.f), 1.f);
        v = p_hs * (d_t - d_s);
    }

    red[threadIdx.x] = v; __syncthreads();
    for (int s = 64; s > 0; s >>= 1) {
        if (threadIdx.x < s) red[threadIdx.x] += red[threadIdx.x + s];
        __syncthreads();
    }
    if (threadIdx.x == 0)
        g_part[bin * QB_CAP + blockIdx.x] = red[0];
}

// ---------------- K5: final ----------------
__global__ void final_kernel(float* __restrict__ out, int nqb, int NMC)
{
    int lane = threadIdx.x;  // 32 threads
    float ec = 0.f;
    for (int bin = 0; bin < NUM_BINS; bin++) {
        float s = 0.f;
        for (int j = lane; j < nqb; j += 32) s += g_part[bin * QB_CAP + j];
        #pragma unroll
        for (int o = 16; o > 0; o >>= 1) s += __shfl_xor_sync(0xffffffff, s, o);
        float integral = (s / (float)NMC) * 100.0f;   // VOLUME
        float ter = g_te_rate[bin];
        if (ter > 0.f) ec += ter * fabsf(integral);
    }
    if (lane == 0) out[0] = ec;
}

// ---------------- launch ----------------
extern "C" void kernel_launch(void* const* d_in, const int* in_sizes, int n_in,
                              void* d_out, int out_size)
{
    const float* bx   = (const float*)d_in[0];
    const int*   y    = (const int*)  d_in[1];
    const int*   pred = (const int*)  d_in[2];
    const float* trp  = (const float*)d_in[3];
    const float* tep  = (const float*)d_in[4];
    const float* trx  = (const float*)d_in[5];
    const float* tex  = (const float*)d_in[6];
    const float* W    = (const float*)d_in[7];
    const float* bv   = (const float*)d_in[8];
    const float* mc   = (const float*)d_in[9];

    int B    = in_sizes[1];
    int NTR  = in_sizes[3];
    int NTE  = in_sizes[4];
    int NTRX = in_sizes[5] / 2;
    int NTEX = in_sizes[6] / 2;
    int NMC  = in_sizes[9] / (2 * NUM_BINS);
    int nqb  = (NMC + 127) / 128;

    init_kernel<<<1, 32>>>();
    hist_kernel<<<25, 256>>>(trp, tep, y, pred, NTR, NTE, B);
    filter_kernel<<<NUM_BINS, 1024>>>(mc, W, bv, NMC, NTR, NTE);

    dim3 mg(nqb, NUM_BINS, DSPLIT);
    main_kernel<<<mg, 128>>>(trx, tex, bx, y, pred, NTRX, NTEX, B);

    dim3 cg(nqb, NUM_BINS);
    combine_kernel<<<cg, 128>>>(NTRX, NTEX, B);

    final_kernel<<<1, 32>>>((float*)d_out, nqb, NMC);
}

// round 9
// speedup vs baseline: 8.6628x; 1.2362x over previous
#include <cuda_runtime.h>

#define NUM_BINS 15
#define NMC_CAP  10240
#define QB_CAP   80      // ceil(NMC_CAP/128)
#define DSPLIT   32
#define TILE     512
#define HTR_B    16
#define HTE_B    8

#define STEP (1.0f / 15.0f)
#define C2   (1.4426950408889634f / 0.18f)   /* log2e / (2*BW*BW) */
#define KN   (0.5654866776461628f)           /* 2*pi*BW*BW */

// ---------------- device scratch ----------------
__device__ int    g_hist_tr_p[HTR_B][NUM_BINS];
__device__ int    g_hist_te_p[HTE_B][NUM_BINS];
__device__ int    g_correct;
__device__ float  g_tr_rate[NUM_BINS];
__device__ float  g_te_rate[NUM_BINS];
__device__ float  g_cntf;
__device__ int    g_qcnt[NUM_BINS];
__device__ float2 g_q[NUM_BINS * NMC_CAP];
__device__ float  g_ssum[DSPLIT * 3 * NUM_BINS * NMC_CAP];  // ~59 MB
__device__ float  g_part[NUM_BINS * QB_CAP];

__device__ __forceinline__ float ex2_approx(float x) {
    float r;
    asm("ex2.approx.ftz.f32 %0, %1;" : "=f"(r) : "f"(x));
    return r;
}

// hat_s = max softmax(x@W + b); membership in bin's [lo,hi] (inclusive)
__device__ __forceinline__ bool pass_bin(float qx, float qy,
                                         const float* __restrict__ W,
                                         const float* __restrict__ bv,
                                         int bin) {
    float l[10];
    float lmax = -1e30f;
    #pragma unroll
    for (int c = 0; c < 10; c++) {
        l[c] = fmaf(qx, W[c], fmaf(qy, W[10 + c], bv[c]));
        lmax = fmaxf(lmax, l[c]);
    }
    float s = 0.f;
    #pragma unroll
    for (int c = 0; c < 10; c++) s += __expf(l[c] - lmax);
    float hs = 1.f / s;
    float lo = bin * STEP;
    float hi = (bin + 1) * STEP;
    return (hs >= lo) && (hs <= hi);
}

// ---------------- K1: histogram partials + correct count (no atomics) --------
__global__ void __launch_bounds__(256) hist_kernel(
    const float* __restrict__ trp, const float* __restrict__ tep,
    const int* __restrict__ y, const int* __restrict__ pred,
    int NTR, int NTE, int B)
{
    __shared__ int sh[NUM_BINS];
    int tid = threadIdx.x;
    int part = blockIdx.x;   // 0..15 train, 16..23 test, 24 correct

    if (part < HTR_B + HTE_B) {
        if (tid < NUM_BINS) sh[tid] = 0;
        __syncthreads();
        const float* src = (part < HTR_B) ? trp : tep;
        int n  = (part < HTR_B) ? NTR : NTE;
        int nb = (part < HTR_B) ? HTR_B : HTE_B;
        int pb = (part < HTR_B) ? part : part - HTR_B;
        for (int i = pb * 256 + tid; i < n; i += nb * 256) {
            float p = src[i];
            int bx = (int)ceilf(p * 15.f) - 1;
            bx = min(14, max(0, bx));
            if (!(p > bx * STEP && p <= (bx + 1) * STEP)) {
                if (p <= bx * STEP) bx--; else bx++;
            }
            if (bx >= 0 && bx < NUM_BINS && p > bx * STEP && p <= (bx + 1) * STEP)
                atomicAdd(&sh[bx], 1);
        }
        __syncthreads();
        if (tid < NUM_BINS) {
            if (part < HTR_B) g_hist_tr_p[part][tid] = sh[tid];
            else              g_hist_te_p[part - HTR_B][tid] = sh[tid];
        }
    } else {
        __shared__ int red[256];
        int c = 0;
        for (int i = tid; i < B; i += 256)
            c += (y[i] == pred[i]) ? 1 : 0;
        red[tid] = c; __syncthreads();
        for (int s = 128; s > 0; s >>= 1) {
            if (tid < s) red[tid] += red[tid + s];
            __syncthreads();
        }
        if (tid == 0) g_correct = red[0];
    }
}

// ---------------- K2: fused filter + deterministic compaction + rates --------
__global__ void __launch_bounds__(1024) filter_kernel(
    const float* __restrict__ mc, const float* __restrict__ W,
    const float* __restrict__ bv, int NMC, int NTR, int NTE)
{
    __shared__ int wtot[32];
    __shared__ int wbase[32];
    __shared__ int runbase;

    const int bin  = blockIdx.x;
    const int tid  = threadIdx.x;
    const int lane = tid & 31;
    const int wid  = tid >> 5;

    if (tid == 0) runbase = 0;
    __syncthreads();

    for (int base = 0; base < NMC; base += 1024) {
        int qi = base + tid;
        bool p = false;
        float qx = 0.f, qy = 0.f;
        if (qi < NMC) {
            qx = mc[(size_t)(bin * NMC + qi) * 2 + 0];
            qy = mc[(size_t)(bin * NMC + qi) * 2 + 1];
            p = pass_bin(qx, qy, W, bv, bin);
        }
        unsigned mask = __ballot_sync(0xffffffffu, p);
        int off = __popc(mask & ((1u << lane) - 1u));
        if (lane == 0) wtot[wid] = __popc(mask);
        __syncthreads();
        if (tid == 0) {
            int r = runbase;
            #pragma unroll
            for (int w = 0; w < 32; w++) { wbase[w] = r; r += wtot[w]; }
            runbase = r;
        }
        __syncthreads();
        if (p)
            g_q[bin * NMC_CAP + wbase[wid] + off] = make_float2(qx, qy);
        __syncthreads();
    }

    if (tid == 0) {
        g_qcnt[bin] = runbase;
        int htr = 0, hte = 0;
        #pragma unroll
        for (int k = 0; k < HTR_B; k++) htr += g_hist_tr_p[k][bin];
        #pragma unroll
        for (int k = 0; k < HTE_B; k++) hte += g_hist_te_p[k][bin];
        g_tr_rate[bin] = (float)htr / (float)NTR;
        g_te_rate[bin] = (float)hte / (float)NTE;
        if (bin == 0) g_cntf = (float)g_correct;
    }
}

// ---------------- K3: KDE main over compacted queries ----------------
__global__ void __launch_bounds__(128) main_kernel(
    const float* __restrict__ trx, const float* __restrict__ tex,
    const float* __restrict__ bx,
    const int* __restrict__ y, const int* __restrict__ pred,
    int NTRX, int NTEX, int B)
{
    __shared__ float4 sd[TILE];

    const int bin = blockIdx.y;
    const int z   = blockIdx.z;
    const int cnt = g_qcnt[bin];
    if ((int)(blockIdx.x * 128) >= cnt) return;

    const int  qi  = blockIdx.x * 128 + threadIdx.x;
    const bool act = qi < cnt;
    float2 q = act ? g_q[bin * NMC_CAP + qi] : make_float2(0.f, 0.f);

    const float Cm = 2.f * C2;
    const float A  = -C2 * (q.x * q.x + q.y * q.y);

    #pragma unroll 1
    for (int ph = 0; ph < 3; ph++) {
        const float* src = (ph == 0) ? trx : (ph == 1) ? tex : bx;
        const int    n   = (ph == 0) ? NTRX : (ph == 1) ? NTEX : B;
        const int i0 = (int)(((long long)z * n) / DSPLIT);
        const int i1 = (int)(((long long)(z + 1) * n) / DSPLIT);
        float a0 = 0.f, a1 = 0.f;

        for (int base = i0; base < i1; base += TILE) {
            int m = min(TILE, i1 - base);
            for (int j = threadIdx.x; j < m; j += 128) {
                float dx = src[(size_t)(base + j) * 2 + 0];
                float dy = src[(size_t)(base + j) * 2 + 1];
                float wt = 1.f;
                if (ph == 2) wt = (y[base + j] == pred[base + j]) ? 1.f : 0.f;
                sd[j] = make_float4(Cm * dx, Cm * dy,
                                    -C2 * (dx * dx + dy * dy), wt);
            }
            __syncthreads();

            if (ph < 2) {
                #pragma unroll 8
                for (int j = 0; j < m; j++) {
                    float4 p = sd[j];
                    float arg = fmaf(p.x, q.x, fmaf(p.y, q.y, p.z + A));
                    float e = ex2_approx(arg);
                    if (j & 1) a1 += e; else a0 += e;
                }
            } else {
                #pragma unroll 8
                for (int j = 0; j < m; j++) {
                    float4 p = sd[j];
                    float arg = fmaf(p.x, q.x, fmaf(p.y, q.y, p.z + A));
                    float e = ex2_approx(arg);
                    if (j & 1) a1 = fmaf(e, p.w, a1);
                    else       a0 = fmaf(e, p.w, a0);
                }
            }
            __syncthreads();
        }
        if (act)
            g_ssum[((size_t)(z * 3 + ph) * NUM_BINS + bin) * NMC_CAP + qi] = a0 + a1;
    }
}

// ---------------- K4: combine partials -> per-block v sums ----------------
__global__ void __launch_bounds__(128) combine_kernel(int NTRX, int NTEX, int B)
{
    __shared__ float red[128];
    const int bin = blockIdx.y;
    const int cnt = g_qcnt[bin];
    const int qi  = blockIdx.x * 128 + threadIdx.x;

    float v = 0.f;
    if (qi < cnt) {
        float s0 = 0.f, s1 = 0.f, s2 = 0.f;
        #pragma unroll
        for (int z = 0; z < DSPLIT; z++) {
            s0 += g_ssum[((size_t)(z * 3 + 0) * NUM_BINS + bin) * NMC_CAP + qi];
            s1 += g_ssum[((size_t)(z * 3 + 1) * NUM_BINS + bin) * NMC_CAP + qi];
            s2 += g_ssum[((size_t)(z * 3 + 2) * NUM_BINS + bin) * NMC_CAP + qi];
        }
        float cntf   = g_cntf;
        float kde_tr = s0 / ((float)NTRX * KN);
        float kde_te = s1 / ((float)NTEX * KN);
        float kde_w  = s2 / (fmaxf(cntf, 1.f) * KN);
        float p_y    = cntf / (float)B;

        float ter = g_te_rate[bin];
        float trr = g_tr_rate[bin];
        float d_t = (ter > 0.f) ? (kde_te / ter) : 0.f;  // idx == 1 by construction
        float d_s = (trr > 0.f) ? (kde_tr / trr) : 0.f;

        float p_hs = kde_w * p_y / (kde_tr + 1e-8f);
        p_hs = fminf(fmaxf(p_hs, 0.f), 1.f);
        v = p_hs * (d_t - d_s);
    }

    red[threadIdx.x] = v; __syncthreads();
    for (int s = 64; s > 0; s >>= 1) {
        if (threadIdx.x < s) red[threadIdx.x] += red[threadIdx.x + s];
        __syncthreads();
    }
    if (threadIdx.x == 0)
        g_part[bin * QB_CAP + blockIdx.x] = red[0];
}

// ---------------- K5: final ----------------
__global__ void final_kernel(float* __restrict__ out, int nqb, int NMC)
{
    int lane = threadIdx.x;  // 32 threads
    float ec = 0.f;
    for (int bin = 0; bin < NUM_BINS; bin++) {
        float s = 0.f;
        for (int j = lane; j < nqb; j += 32) s += g_part[bin * QB_CAP + j];
        #pragma unroll
        for (int o = 16; o > 0; o >>= 1) s += __shfl_xor_sync(0xffffffff, s, o);
        float integral = (s / (float)NMC) * 100.0f;   // VOLUME
        float ter = g_te_rate[bin];
        if (ter > 0.f) ec += ter * fabsf(integral);
    }
    if (lane == 0) out[0] = ec;
}

// ---------------- launch ----------------
extern "C" void kernel_launch(void* const* d_in, const int* in_sizes, int n_in,
                              void* d_out, int out_size)
{
    const float* bx   = (const float*)d_in[0];
    const int*   y    = (const int*)  d_in[1];
    const int*   pred = (const int*)  d_in[2];
    const float* trp  = (const float*)d_in[3];
    const float* tep  = (const float*)d_in[4];
    const float* trx  = (const float*)d_in[5];
    const float* tex  = (const float*)d_in[6];
    const float* W    = (const float*)d_in[7];
    const float* bv   = (const float*)d_in[8];
    const float* mc   = (const float*)d_in[9];

    int B    = in_sizes[1];
    int NTR  = in_sizes[3];
    int NTE  = in_sizes[4];
    int NTRX = in_sizes[5] / 2;
    int NTEX = in_sizes[6] / 2;
    int NMC  = in_sizes[9] / (2 * NUM_BINS);
    int nqb  = (NMC + 127) / 128;

    hist_kernel<<<HTR_B + HTE_B + 1, 256>>>(trp, tep, y, pred, NTR, NTE, B);
    filter_kernel<<<NUM_BINS, 1024>>>(mc, W, bv, NMC, NTR, NTE);

    dim3 mg(nqb, NUM_BINS, DSPLIT);
    main_kernel<<<mg, 128>>>(trx, tex, bx, y, pred, NTRX, NTEX, B);

    dim3 cg(nqb, NUM_BINS);
    combine_kernel<<<cg, 128>>>(NTRX, NTEX, B);

    final_kernel<<<1, 32>>>((float*)d_out, nqb, NMC);
}

// round 10
// speedup vs baseline: 9.8678x; 1.1391x over previous
#include <cuda_runtime.h>

#define NUM_BINS 15
#define NMC_CAP  10240
#define QB_CAP   80
#define DSPLIT   32
#define TILE     512          /* points per tile */
#define TPAIRS   (TILE / 2)
#define HTR_B    16
#define HTE_B    8

#define STEP (1.0f / 15.0f)
#define C2   (1.4426950408889634f / 0.18f)   /* log2e / (2*BW*BW) */
#define KN   (0.5654866776461628f)           /* 2*pi*BW*BW */

typedef unsigned long long ull;

// ---------------- device scratch ----------------
__device__ int    g_hist_tr_p[HTR_B][NUM_BINS];
__device__ int    g_hist_te_p[HTE_B][NUM_BINS];
__device__ int    g_correct;
__device__ int    g_qcnt[NUM_BINS];
__device__ float2 g_q[NUM_BINS * NMC_CAP];
__device__ float  g_ssum[DSPLIT * 3 * NUM_BINS * NMC_CAP];  // ~59 MB
__device__ float  g_part[NUM_BINS * QB_CAP];

// ---------------- packed helpers ----------------
#define ADD2(d, a, b)    asm("add.rn.f32x2 %0, %1, %2;"      : "=l"(d) : "l"(a), "l"(b))
#define FMA2(d, a, b, c) asm("fma.rn.f32x2 %0, %1, %2, %3;"  : "=l"(d) : "l"(a), "l"(b), "l"(c))
#define PK2(d, lo, hi)   asm("mov.b64 %0, {%1, %2};"         : "=l"(d) : "f"(lo), "f"(hi))
#define UPK2(lo, hi, s)  asm("mov.b64 {%0, %1}, %2;"         : "=f"(lo), "=f"(hi) : "l"(s))

__device__ __forceinline__ float ex2_approx(float x) {
    float r;
    asm("ex2.approx.ftz.f32 %0, %1;" : "=f"(r) : "f"(x));
    return r;
}

// hat_s = max softmax(x@W + b); membership in bin's [lo,hi] (inclusive)
__device__ __forceinline__ bool pass_bin(float qx, float qy,
                                         const float* __restrict__ W,
                                         const float* __restrict__ bv,
                                         int bin) {
    float l[10];
    float lmax = -1e30f;
    #pragma unroll
    for (int c = 0; c < 10; c++) {
        l[c] = fmaf(qx, W[c], fmaf(qy, W[10 + c], bv[c]));
        lmax = fmaxf(lmax, l[c]);
    }
    float s = 0.f;
    #pragma unroll
    for (int c = 0; c < 10; c++) s += __expf(l[c] - lmax);
    float hs = 1.f / s;
    float lo = bin * STEP;
    float hi = (bin + 1) * STEP;
    return (hs >= lo) && (hs <= hi);
}

// ---------------- K1: fused filter + hist partials + correct ----------------
// blocks 0..14: per-bin compaction; 15..30: train hist; 31..38: test hist; 39: correct
__global__ void __launch_bounds__(1024) prep_kernel(
    const float* __restrict__ mc, const float* __restrict__ W,
    const float* __restrict__ bv,
    const float* __restrict__ trp, const float* __restrict__ tep,
    const int* __restrict__ y, const int* __restrict__ pred,
    int NMC, int NTR, int NTE, int B)
{
    const int part = blockIdx.x;
    const int tid  = threadIdx.x;

    if (part < NUM_BINS) {
        __shared__ int wtot[32];
        __shared__ int wbase[32];
        __shared__ int runbase;
        const int bin  = part;
        const int lane = tid & 31;
        const int wid  = tid >> 5;
        if (tid == 0) runbase = 0;
        __syncthreads();

        for (int base = 0; base < NMC; base += 1024) {
            int qi = base + tid;
            bool p = false;
            float qx = 0.f, qy = 0.f;
            if (qi < NMC) {
                qx = mc[(size_t)(bin * NMC + qi) * 2 + 0];
                qy = mc[(size_t)(bin * NMC + qi) * 2 + 1];
                p = pass_bin(qx, qy, W, bv, bin);
            }
            unsigned mask = __ballot_sync(0xffffffffu, p);
            int off = __popc(mask & ((1u << lane) - 1u));
            if (lane == 0) wtot[wid] = __popc(mask);
            __syncthreads();
            if (tid == 0) {
                int r = runbase;
                #pragma unroll
                for (int w = 0; w < 32; w++) { wbase[w] = r; r += wtot[w]; }
                runbase = r;
            }
            __syncthreads();
            if (p)
                g_q[bin * NMC_CAP + wbase[wid] + off] = make_float2(qx, qy);
            __syncthreads();
        }
        if (tid == 0) g_qcnt[bin] = runbase;
    } else if (part < NUM_BINS + HTR_B + HTE_B) {
        __shared__ int sh[NUM_BINS];
        if (tid < NUM_BINS) sh[tid] = 0;
        __syncthreads();
        bool is_tr = (part < NUM_BINS + HTR_B);
        const float* src = is_tr ? trp : tep;
        int n  = is_tr ? NTR : NTE;
        int nb = is_tr ? HTR_B : HTE_B;
        int pb = is_tr ? (part - NUM_BINS) : (part - NUM_BINS - HTR_B);
        for (int i = pb * 1024 + tid; i < n; i += nb * 1024) {
            float p = src[i];
            int bx = (int)ceilf(p * 15.f) - 1;
            bx = min(14, max(0, bx));
            if (!(p > bx * STEP && p <= (bx + 1) * STEP)) {
                if (p <= bx * STEP) bx--; else bx++;
            }
            if (bx >= 0 && bx < NUM_BINS && p > bx * STEP && p <= (bx + 1) * STEP)
                atomicAdd(&sh[bx], 1);
        }
        __syncthreads();
        if (tid < NUM_BINS) {
            if (is_tr) g_hist_tr_p[pb][tid] = sh[tid];
            else       g_hist_te_p[pb][tid] = sh[tid];
        }
    } else {
        __shared__ int red[1024];
        int c = 0;
        for (int i = tid; i < B; i += 1024)
            c += (y[i] == pred[i]) ? 1 : 0;
        red[tid] = c; __syncthreads();
        for (int s = 512; s > 0; s >>= 1) {
            if (tid < s) red[tid] += red[tid + s];
            __syncthreads();
        }
        if (tid == 0) g_correct = red[0];
    }
}

// ---------------- K2: KDE main (f16x2 EX2 for phases 0/1, fp32 for phase 2) --
__global__ void __launch_bounds__(128) main_kernel(
    const float* __restrict__ trx, const float* __restrict__ tex,
    const float* __restrict__ bx,
    const int* __restrict__ y, const int* __restrict__ pred,
    int NTRX, int NTEX, int B)
{
    __shared__ __align__(16) unsigned char sraw[TILE * 16];  // 8 KB, unioned
    float4* sP  = (float4*)sraw;                  // [TPAIRS] (cmx0,cmx1,cmy0,cmy1)
    float2* sZ  = (float2*)(sraw + TPAIRS * 16);  // [TPAIRS] (z0,z1)
    float4* sd  = (float4*)sraw;                  // phase-2 view [TILE]

    const int bin = blockIdx.y;
    const int z   = blockIdx.z;
    const int cnt = g_qcnt[bin];
    if ((int)(blockIdx.x * 128) >= cnt) return;

    const int  qi  = blockIdx.x * 128 + threadIdx.x;
    const bool act = qi < cnt;
    float2 q = act ? g_q[bin * NMC_CAP + qi] : make_float2(0.f, 0.f);

    const float Cm = 2.f * C2;
    const float A  = -C2 * (q.x * q.x + q.y * q.y);
    ull qx2, qy2, A2;
    PK2(qx2, q.x, q.x);
    PK2(qy2, q.y, q.y);
    PK2(A2,  A,   A);

    // ---- phases 0/1: unweighted KDE, f16x2 EX2 ----
    #pragma unroll 1
    for (int ph = 0; ph < 2; ph++) {
        const float* src = (ph == 0) ? trx : tex;
        const int    n   = (ph == 0) ? NTRX : NTEX;
        const int np = n / 2;
        const int p0 = (int)(((long long)z * np) / DSPLIT);
        const int p1 = (int)(((long long)(z + 1) * np) / DSPLIT);
        float a0 = 0.f, a1 = 0.f;

        for (int basep = p0; basep < p1; basep += TPAIRS) {
            int mp = min(TPAIRS, p1 - basep);
            for (int jp = threadIdx.x; jp < mp; jp += 128) {
                float4 v = ((const float4*)src)[basep + jp];  // (x0,y0,x1,y1)
                sP[jp] = make_float4(Cm * v.x, Cm * v.z, Cm * v.y, Cm * v.w);
                sZ[jp] = make_float2(-C2 * (v.x * v.x + v.y * v.y),
                                     -C2 * (v.z * v.z + v.w * v.w));
            }
            __syncthreads();

            unsigned hacc = 0u;
            #pragma unroll 8
            for (int jp = 0; jp < mp; jp++) {
                ulonglong2 pp = ((const ulonglong2*)sP)[jp];   // .x=(cmx0,cmx1) .y=(cmy0,cmy1)
                ull pz = ((const ull*)sZ)[jp];
                ull t;
                ADD2(t, pz, A2);
                FMA2(t, pp.y, qy2, t);
                FMA2(t, pp.x, qx2, t);
                float f0, f1;
                UPK2(f0, f1, t);
                unsigned h, e;
                asm("cvt.rn.f16x2.f32 %0, %1, %2;" : "=r"(h) : "f"(f1), "f"(f0));
                asm("ex2.approx.f16x2 %0, %1;" : "=r"(e) : "r"(h));
                asm("add.rn.f16x2 %0, %1, %2;" : "=r"(hacc) : "r"(hacc), "r"(e));
                if ((jp & 15) == 15) {
                    float g0, g1;
                    asm("{.reg .b16 lo,hi; mov.b32 {lo,hi}, %2;"
                        " cvt.f32.f16 %0, lo; cvt.f32.f16 %1, hi;}"
                        : "=f"(g0), "=f"(g1) : "r"(hacc));
                    a0 += g0; a1 += g1; hacc = 0u;
                }
            }
            {   // tail flush
                float g0, g1;
                asm("{.reg .b16 lo,hi; mov.b32 {lo,hi}, %2;"
                    " cvt.f32.f16 %0, lo; cvt.f32.f16 %1, hi;}"
                    : "=f"(g0), "=f"(g1) : "r"(hacc));
                a0 += g0; a1 += g1;
            }
            __syncthreads();
        }
        if (act)
            g_ssum[((size_t)(z * 3 + ph) * NUM_BINS + bin) * NMC_CAP + qi] = a0 + a1;
    }

    // ---- phase 2: weighted KDE over batch (small), exact fp32 ----
    {
        const int np = B / 2;
        const int i0 = 2 * (int)(((long long)z * np) / DSPLIT);
        const int i1 = 2 * (int)(((long long)(z + 1) * np) / DSPLIT);
        float a0 = 0.f, a1 = 0.f;

        for (int base = i0; base < i1; base += TILE) {
            int m = min(TILE, i1 - base);
            for (int j = threadIdx.x; j < m; j += 128) {
                float dx = bx[(size_t)(base + j) * 2 + 0];
                float dy = bx[(size_t)(base + j) * 2 + 1];
                float wt = (y[base + j] == pred[base + j]) ? 1.f : 0.f;
                sd[j] = make_float4(Cm * dx, Cm * dy,
                                    -C2 * (dx * dx + dy * dy), wt);
            }
            __syncthreads();
            #pragma unroll 8
            for (int j = 0; j < m; j++) {
                float4 p = sd[j];
                float arg = fmaf(p.x, q.x, fmaf(p.y, q.y, p.z + A));
                float e = ex2_approx(arg);
                if (j & 1) a1 = fmaf(e, p.w, a1);
                else       a0 = fmaf(e, p.w, a0);
            }
            __syncthreads();
        }
        if (act)
            g_ssum[((size_t)(z * 3 + 2) * NUM_BINS + bin) * NMC_CAP + qi] = a0 + a1;
    }
}

// ---------------- K3: combine partials -> per-block v sums ----------------
__global__ void __launch_bounds__(128) combine_kernel(int NTRX, int NTEX, int B,
                                                      int NTR, int NTE)
{
    __shared__ float red[128];
    const int bin = blockIdx.y;
    const int cnt = g_qcnt[bin];
    const int qi  = blockIdx.x * 128 + threadIdx.x;

    float v = 0.f;
    if (qi < cnt) {
        float s0 = 0.f, s1 = 0.f, s2 = 0.f;
        #pragma unroll
        for (int zz = 0; zz < DSPLIT; zz++) {
            s0 += g_ssum[((size_t)(zz * 3 + 0) * NUM_BINS + bin) * NMC_CAP + qi];
            s1 += g_ssum[((size_t)(zz * 3 + 1) * NUM_BINS + bin) * NMC_CAP + qi];
            s2 += g_ssum[((size_t)(zz * 3 + 2) * NUM_BINS + bin) * NMC_CAP + qi];
        }
        int htr = 0, hte = 0;
        #pragma unroll
        for (int k = 0; k < HTR_B; k++) htr += g_hist_tr_p[k][bin];
        #pragma unroll
        for (int k = 0; k < HTE_B; k++) hte += g_hist_te_p[k][bin];
        float trr = (float)htr / (float)NTR;
        float ter = (float)hte / (float)NTE;
        float cntf = (float)g_correct;

        float kde_tr = s0 / ((float)NTRX * KN);
        float kde_te = s1 / ((float)NTEX * KN);
        float kde_w  = s2 / (fmaxf(cntf, 1.f) * KN);
        float p_y    = cntf / (float)B;

        float d_t = (ter > 0.f) ? (kde_te / ter) : 0.f;  // idx == 1 by construction
        float d_s = (trr > 0.f) ? (kde_tr / trr) : 0.f;

        float p_hs = kde_w * p_y / (kde_tr + 1e-8f);
        p_hs = fminf(fmaxf(p_hs, 0.f), 1.f);
        v = p_hs * (d_t - d_s);
    }

    red[threadIdx.x] = v; __syncthreads();
    for (int s = 64; s > 0; s >>= 1) {
        if (threadIdx.x < s) red[threadIdx.x] += red[threadIdx.x + s];
        __syncthreads();
    }
    if (threadIdx.x == 0)
        g_part[bin * QB_CAP + blockIdx.x] = red[0];
}

// ---------------- K4: final ----------------
__global__ void final_kernel(float* __restrict__ out, int nqb, int NMC, int NTE)
{
    int lane = threadIdx.x;  // 32 threads
    float ec = 0.f;
    for (int bin = 0; bin < NUM_BINS; bin++) {
        float s = 0.f;
        for (int j = lane; j < nqb; j += 32) s += g_part[bin * QB_CAP + j];
        #pragma unroll
        for (int o = 16; o > 0; o >>= 1) s += __shfl_xor_sync(0xffffffff, s, o);
        int hte = 0;
        #pragma unroll
        for (int k = 0; k < HTE_B; k++) hte += g_hist_te_p[k][bin];
        float ter = (float)hte / (float)NTE;
        float integral = (s / (float)NMC) * 100.0f;   // VOLUME
        if (ter > 0.f) ec += ter * fabsf(integral);
    }
    if (lane == 0) out[0] = ec;
}

// ---------------- launch ----------------
extern "C" void kernel_launch(void* const* d_in, const int* in_sizes, int n_in,
                              void* d_out, int out_size)
{
    const float* bx   = (const float*)d_in[0];
    const int*   y    = (const int*)  d_in[1];
    const int*   pred = (const int*)  d_in[2];
    const float* trp  = (const float*)d_in[3];
    const float* tep  = (const float*)d_in[4];
    const float* trx  = (const float*)d_in[5];
    const float* tex  = (const float*)d_in[6];
    const float* W    = (const float*)d_in[7];
    const float* bv   = (const float*)d_in[8];
    const float* mc   = (const float*)d_in[9];

    int B    = in_sizes[1];
    int NTR  = in_sizes[3];
    int NTE  = in_sizes[4];
    int NTRX = in_sizes[5] / 2;
    int NTEX = in_sizes[6] / 2;
    int NMC  = in_sizes[9] / (2 * NUM_BINS);
    int nqb  = (NMC + 127) / 128;

    prep_kernel<<<NUM_BINS + HTR_B + HTE_B + 1, 1024>>>(
        mc, W, bv, trp, tep, y, pred, NMC, NTR, NTE, B);

    dim3 mg(nqb, NUM_BINS, DSPLIT);
    main_kernel<<<mg, 128>>>(trx, tex, bx, y, pred, NTRX, NTEX, B);

    dim3 cg(nqb, NUM_BINS);
    combine_kernel<<<cg, 128>>>(NTRX, NTEX, B, NTR, NTE);

    final_kernel<<<1, 32>>>((float*)d_out, nqb, NMC, NTE);
}

// round 11
// speedup vs baseline: 10.2771x; 1.0415x over previous
#include <cuda_runtime.h>

#define NUM_BINS 15
#define NMC_CAP  10240
#define QB_CAP   80
#define DSPLIT   32
#define TILE     512          /* points per tile */
#define TPAIRS   (TILE / 2)
#define HTR_B    16
#define HTE_B    8

#define STEP (1.0f / 15.0f)
#define C2   (1.4426950408889634f / 0.18f)   /* log2e / (2*BW*BW) */
#define KN   (0.5654866776461628f)           /* 2*pi*BW*BW */

typedef unsigned long long ull;

// ---------------- device scratch ----------------
__device__ int    g_hist_tr_p[HTR_B][NUM_BINS];
__device__ int    g_hist_te_p[HTE_B][NUM_BINS];
__device__ int    g_correct;
__device__ int    g_qcnt[NUM_BINS];
__device__ float2 g_q[NUM_BINS * NMC_CAP];
// layout: [ (bin*NMC_CAP + qi)*3 + ph ] * DSPLIT + z   (combine reads contiguous)
__device__ float  g_ssum[(size_t)NUM_BINS * NMC_CAP * 3 * DSPLIT];  // ~59 MB
__device__ float  g_part[NUM_BINS * QB_CAP];

// ---------------- packed helpers ----------------
#define ADD2(d, a, b)    asm("add.rn.f32x2 %0, %1, %2;"      : "=l"(d) : "l"(a), "l"(b))
#define FMA2(d, a, b, c) asm("fma.rn.f32x2 %0, %1, %2, %3;"  : "=l"(d) : "l"(a), "l"(b), "l"(c))
#define PK2(d, lo, hi)   asm("mov.b64 %0, {%1, %2};"         : "=l"(d) : "f"(lo), "f"(hi))
#define UPK2(lo, hi, s)  asm("mov.b64 {%0, %1}, %2;"         : "=f"(lo), "=f"(hi) : "l"(s))

__device__ __forceinline__ float ex2_approx(float x) {
    float r;
    asm("ex2.approx.ftz.f32 %0, %1;" : "=f"(r) : "f"(x));
    return r;
}

// hat_s = max softmax(x@W + b); membership in bin's [lo,hi] (inclusive)
__device__ __forceinline__ bool pass_bin(float qx, float qy,
                                         const float* __restrict__ W,
                                         const float* __restrict__ bv,
                                         int bin) {
    float l[10];
    float lmax = -1e30f;
    #pragma unroll
    for (int c = 0; c < 10; c++) {
        l[c] = fmaf(qx, W[c], fmaf(qy, W[10 + c], bv[c]));
        lmax = fmaxf(lmax, l[c]);
    }
    float s = 0.f;
    #pragma unroll
    for (int c = 0; c < 10; c++) s += __expf(l[c] - lmax);
    float hs = 1.f / s;
    float lo = bin * STEP;
    float hi = (bin + 1) * STEP;
    return (hs >= lo) && (hs <= hi);
}

// ---------------- K1: fused filter + hist partials + correct ----------------
__global__ void __launch_bounds__(1024) prep_kernel(
    const float* __restrict__ mc, const float* __restrict__ W,
    const float* __restrict__ bv,
    const float* __restrict__ trp, const float* __restrict__ tep,
    const int* __restrict__ y, const int* __restrict__ pred,
    int NMC, int NTR, int NTE, int B)
{
    const int part = blockIdx.x;
    const int tid  = threadIdx.x;

    if (part < NUM_BINS) {
        __shared__ int wtot[32];
        __shared__ int wbase[32];
        __shared__ int runbase;
        const int bin  = part;
        const int lane = tid & 31;
        const int wid  = tid >> 5;
        if (tid == 0) runbase = 0;
        __syncthreads();

        for (int base = 0; base < NMC; base += 1024) {
            int qi = base + tid;
            bool p = false;
            float qx = 0.f, qy = 0.f;
            if (qi < NMC) {
                qx = mc[(size_t)(bin * NMC + qi) * 2 + 0];
                qy = mc[(size_t)(bin * NMC + qi) * 2 + 1];
                p = pass_bin(qx, qy, W, bv, bin);
            }
            unsigned mask = __ballot_sync(0xffffffffu, p);
            int off = __popc(mask & ((1u << lane) - 1u));
            if (lane == 0) wtot[wid] = __popc(mask);
            __syncthreads();
            if (tid == 0) {
                int r = runbase;
                #pragma unroll
                for (int w = 0; w < 32; w++) { wbase[w] = r; r += wtot[w]; }
                runbase = r;
            }
            __syncthreads();
            if (p)
                g_q[bin * NMC_CAP + wbase[wid] + off] = make_float2(qx, qy);
            __syncthreads();
        }
        if (tid == 0) g_qcnt[bin] = runbase;
    } else if (part < NUM_BINS + HTR_B + HTE_B) {
        __shared__ int sh[NUM_BINS];
        if (tid < NUM_BINS) sh[tid] = 0;
        __syncthreads();
        bool is_tr = (part < NUM_BINS + HTR_B);
        const float* src = is_tr ? trp : tep;
        int n  = is_tr ? NTR : NTE;
        int nb = is_tr ? HTR_B : HTE_B;
        int pb = is_tr ? (part - NUM_BINS) : (part - NUM_BINS - HTR_B);
        for (int i = pb * 1024 + tid; i < n; i += nb * 1024) {
            float p = src[i];
            int bx = (int)ceilf(p * 15.f) - 1;
            bx = min(14, max(0, bx));
            if (!(p > bx * STEP && p <= (bx + 1) * STEP)) {
                if (p <= bx * STEP) bx--; else bx++;
            }
            if (bx >= 0 && bx < NUM_BINS && p > bx * STEP && p <= (bx + 1) * STEP)
                atomicAdd(&sh[bx], 1);
        }
        __syncthreads();
        if (tid < NUM_BINS) {
            if (is_tr) g_hist_tr_p[pb][tid] = sh[tid];
            else       g_hist_te_p[pb][tid] = sh[tid];
        }
    } else {
        __shared__ int red[1024];
        int c = 0;
        for (int i = tid; i < B; i += 1024)
            c += (y[i] == pred[i]) ? 1 : 0;
        red[tid] = c; __syncthreads();
        for (int s = 512; s > 0; s >>= 1) {
            if (tid < s) red[tid] += red[tid + s];
            __syncthreads();
        }
        if (tid == 0) g_correct = red[0];
    }
}

// ---------------- K2: KDE main (f16x2 EX2 for phases 0/1, fp32 for phase 2) --
__global__ void __launch_bounds__(128) main_kernel(
    const float* __restrict__ trx, const float* __restrict__ tex,
    const float* __restrict__ bx,
    const int* __restrict__ y, const int* __restrict__ pred,
    int NTRX, int NTEX, int B)
{
    __shared__ __align__(16) unsigned char sraw[TILE * 16];  // 8 KB, unioned
    float4* sP  = (float4*)sraw;                  // [TPAIRS] (cmx0,cmx1,cmy0,cmy1)
    float2* sZ  = (float2*)(sraw + TPAIRS * 16);  // [TPAIRS] (z0,z1)
    float4* sd  = (float4*)sraw;                  // phase-2 view [TILE]

    const int bin = blockIdx.y;
    const int z   = blockIdx.z;
    const int cnt = g_qcnt[bin];
    if ((int)(blockIdx.x * 128) >= cnt) return;

    const int  qi  = blockIdx.x * 128 + threadIdx.x;
    const bool act = qi < cnt;
    float2 q = act ? g_q[bin * NMC_CAP + qi] : make_float2(0.f, 0.f);

    const size_t obase = ((size_t)(bin * NMC_CAP + qi) * 3) * DSPLIT + z;

    const float Cm = 2.f * C2;
    const float A  = -C2 * (q.x * q.x + q.y * q.y);
    ull qx2, qy2, A2;
    PK2(qx2, q.x, q.x);
    PK2(qy2, q.y, q.y);
    PK2(A2,  A,   A);

    // ---- phases 0/1: unweighted KDE, f16x2 EX2 ----
    #pragma unroll 1
    for (int ph = 0; ph < 2; ph++) {
        const float* src = (ph == 0) ? trx : tex;
        const int    n   = (ph == 0) ? NTRX : NTEX;
        const int np = n / 2;
        const int p0 = (int)(((long long)z * np) / DSPLIT);
        const int p1 = (int)(((long long)(z + 1) * np) / DSPLIT);
        float a0 = 0.f, a1 = 0.f;

        for (int basep = p0; basep < p1; basep += TPAIRS) {
            int mp = min(TPAIRS, p1 - basep);
            for (int jp = threadIdx.x; jp < mp; jp += 128) {
                float4 v = ((const float4*)src)[basep + jp];  // (x0,y0,x1,y1)
                sP[jp] = make_float4(Cm * v.x, Cm * v.z, Cm * v.y, Cm * v.w);
                sZ[jp] = make_float2(-C2 * (v.x * v.x + v.y * v.y),
                                     -C2 * (v.z * v.z + v.w * v.w));
            }
            __syncthreads();

            unsigned hacc = 0u;
            #pragma unroll 16
            for (int jp = 0; jp < mp; jp++) {
                ulonglong2 pp = ((const ulonglong2*)sP)[jp];
                ull pz = ((const ull*)sZ)[jp];
                ull t;
                ADD2(t, pz, A2);
                FMA2(t, pp.y, qy2, t);
                FMA2(t, pp.x, qx2, t);
                float f0, f1;
                UPK2(f0, f1, t);
                unsigned h, e;
                asm("cvt.rn.f16x2.f32 %0, %1, %2;" : "=r"(h) : "f"(f1), "f"(f0));
                asm("ex2.approx.f16x2 %0, %1;" : "=r"(e) : "r"(h));
                asm("add.rn.f16x2 %0, %1, %2;" : "=r"(hacc) : "r"(hacc), "r"(e));
                if ((jp & 15) == 15) {
                    float g0, g1;
                    asm("{.reg .b16 lo,hi; mov.b32 {lo,hi}, %2;"
                        " cvt.f32.f16 %0, lo; cvt.f32.f16 %1, hi;}"
                        : "=f"(g0), "=f"(g1) : "r"(hacc));
                    a0 += g0; a1 += g1; hacc = 0u;
                }
            }
            {   // tail flush
                float g0, g1;
                asm("{.reg .b16 lo,hi; mov.b32 {lo,hi}, %2;"
                    " cvt.f32.f16 %0, lo; cvt.f32.f16 %1, hi;}"
                    : "=f"(g0), "=f"(g1) : "r"(hacc));
                a0 += g0; a1 += g1;
            }
            __syncthreads();
        }
        if (act)
            g_ssum[obase + (size_t)ph * DSPLIT] = a0 + a1;
    }

    // ---- phase 2: weighted KDE over batch (small), exact fp32 ----
    {
        const int np = B / 2;
        const int i0 = 2 * (int)(((long long)z * np) / DSPLIT);
        const int i1 = 2 * (int)(((long long)(z + 1) * np) / DSPLIT);
        float a0 = 0.f, a1 = 0.f;

        for (int base = i0; base < i1; base += TILE) {
            int m = min(TILE, i1 - base);
            for (int j = threadIdx.x; j < m; j += 128) {
                float dx = bx[(size_t)(base + j) * 2 + 0];
                float dy = bx[(size_t)(base + j) * 2 + 1];
                float wt = (y[base + j] == pred[base + j]) ? 1.f : 0.f;
                sd[j] = make_float4(Cm * dx, Cm * dy,
                                    -C2 * (dx * dx + dy * dy), wt);
            }
            __syncthreads();
            #pragma unroll 8
            for (int j = 0; j < m; j++) {
                float4 p = sd[j];
                float arg = fmaf(p.x, q.x, fmaf(p.y, q.y, p.z + A));
                float e = ex2_approx(arg);
                if (j & 1) a1 = fmaf(e, p.w, a1);
                else       a0 = fmaf(e, p.w, a0);
            }
            __syncthreads();
        }
        if (act)
            g_ssum[obase + (size_t)2 * DSPLIT] = a0 + a1;
    }
}

// ---------------- K3: combine partials -> per-block v sums ----------------
__global__ void __launch_bounds__(128) combine_kernel(int NTRX, int NTEX, int B,
                                                      int NTR, int NTE)
{
    __shared__ float red[128];
    const int bin = blockIdx.y;
    const int cnt = g_qcnt[bin];
    const int qi  = blockIdx.x * 128 + threadIdx.x;

    float v = 0.f;
    if (qi < cnt) {
        const size_t obase = ((size_t)(bin * NMC_CAP + qi) * 3) * DSPLIT;
        float s0 = 0.f, s1 = 0.f, s2 = 0.f;
        #pragma unroll
        for (int zz = 0; zz < DSPLIT; zz++) s0 += g_ssum[obase + zz];
        #pragma unroll
        for (int zz = 0; zz < DSPLIT; zz++) s1 += g_ssum[obase + DSPLIT + zz];
        #pragma unroll
        for (int zz = 0; zz < DSPLIT; zz++) s2 += g_ssum[obase + 2 * DSPLIT + zz];

        int htr = 0, hte = 0;
        #pragma unroll
        for (int k = 0; k < HTR_B; k++) htr += g_hist_tr_p[k][bin];
        #pragma unroll
        for (int k = 0; k < HTE_B; k++) hte += g_hist_te_p[k][bin];
        float trr = (float)htr / (float)NTR;
        float ter = (float)hte / (float)NTE;
        float cntf = (float)g_correct;

        float kde_tr = s0 / ((float)NTRX * KN);
        float kde_te = s1 / ((float)NTEX * KN);
        float kde_w  = s2 / (fmaxf(cntf, 1.f) * KN);
        float p_y    = cntf / (float)B;

        float d_t = (ter > 0.f) ? (kde_te / ter) : 0.f;  // idx == 1 by construction
        float d_s = (trr > 0.f) ? (kde_tr / trr) : 0.f;

        float p_hs = kde_w * p_y / (kde_tr + 1e-8f);
        p_hs = fminf(fmaxf(p_hs, 0.f), 1.f);
        v = p_hs * (d_t - d_s);
    }

    red[threadIdx.x] = v; __syncthreads();
    for (int s = 64; s > 0; s >>= 1) {
        if (threadIdx.x < s) red[threadIdx.x] += red[threadIdx.x + s];
        __syncthreads();
    }
    if (threadIdx.x == 0)
        g_part[bin * QB_CAP + blockIdx.x] = red[0];
}

// ---------------- K4: final (one warp per bin, parallel) ----------------
__global__ void __launch_bounds__(NUM_BINS * 32) final_kernel(
    float* __restrict__ out, int nqb, int NMC, int NTE)
{
    __shared__ float sbin[NUM_BINS];
    const int bin  = threadIdx.x >> 5;
    const int lane = threadIdx.x & 31;

    float s = 0.f;
    for (int j = lane; j < nqb; j += 32) s += g_part[bin * QB_CAP + j];
    #pragma unroll
    for (int o = 16; o > 0; o >>= 1) s += __shfl_xor_sync(0xffffffff, s, o);

    if (lane == 0) {
        int hte = 0;
        #pragma unroll
        for (int k = 0; k < HTE_B; k++) hte += g_hist_te_p[k][bin];
        float ter = (float)hte / (float)NTE;
        float integral = (s / (float)NMC) * 100.0f;   // VOLUME
        sbin[bin] = (ter > 0.f) ? ter * fabsf(integral) : 0.f;
    }
    __syncthreads();
    if (threadIdx.x == 0) {
        float ec = 0.f;
        #pragma unroll
        for (int b = 0; b < NUM_BINS; b++) ec += sbin[b];
        out[0] = ec;
    }
}

// ---------------- launch ----------------
extern "C" void kernel_launch(void* const* d_in, const int* in_sizes, int n_in,
                              void* d_out, int out_size)
{
    const float* bx   = (const float*)d_in[0];
    const int*   y    = (const int*)  d_in[1];
    const int*   pred = (const int*)  d_in[2];
    const float* trp  = (const float*)d_in[3];
    const float* tep  = (const float*)d_in[4];
    const float* trx  = (const float*)d_in[5];
    const float* tex  = (const float*)d_in[6];
    const float* W    = (const float*)d_in[7];
    const float* bv   = (const float*)d_in[8];
    const float* mc   = (const float*)d_in[9];

    int B    = in_sizes[1];
    int NTR  = in_sizes[3];
    int NTE  = in_sizes[4];
    int NTRX = in_sizes[5] / 2;
    int NTEX = in_sizes[6] / 2;
    int NMC  = in_sizes[9] / (2 * NUM_BINS);
    int nqb  = (NMC + 127) / 128;

    prep_kernel<<<NUM_BINS + HTR_B + HTE_B + 1, 1024>>>(
        mc, W, bv, trp, tep, y, pred, NMC, NTR, NTE, B);

    dim3 mg(nqb, NUM_BINS, DSPLIT);
    main_kernel<<<mg, 128>>>(trx, tex, bx, y, pred, NTRX, NTEX, B);

    dim3 cg(nqb, NUM_BINS);
    combine_kernel<<<cg, 128>>>(NTRX, NTEX, B, NTR, NTE);

    final_kernel<<<1, NUM_BINS * 32>>>((float*)d_out, nqb, NMC, NTE);
}